// round 1
// baseline (speedup 1.0000x reference)
#include <cuda_runtime.h>
#include <cuda_bf16.h>

#define BB 64
#define NN 2048
#define DD 256
#define EPS 1e-05f

// Scratch for per-batch (sum, sumsq). No cudaMalloc allowed -> device global.
__device__ float g_stats[2 * BB];

__global__ void zero_stats_kernel() {
    int t = threadIdx.x;
    if (t < 2 * BB) g_stats[t] = 0.0f;
}

// Pass 1: per-batch sum and sum-of-squares over valid rows only.
// grid = (CHUNKS, B), block = 256 threads. Each chunk covers ROWS_PER_CHUNK rows.
#define CHUNKS 16
#define ROWS_PER_CHUNK (NN / CHUNKS)  // 128
__global__ __launch_bounds__(256) void stats_kernel(const float* __restrict__ x,
                                                    const int* __restrict__ lengths) {
    const int b = blockIdx.y;
    const int len = lengths[b];
    const int row0 = blockIdx.x * ROWS_PER_CHUNK;
    const int row1 = min(row0 + ROWS_PER_CHUNK, len);

    float s = 0.0f, ss = 0.0f;
    if (row1 > row0) {
        const float4* __restrict__ p =
            reinterpret_cast<const float4*>(x + (size_t)b * NN * DD) + (size_t)row0 * (DD / 4);
        const int nvec = (row1 - row0) * (DD / 4);
        for (int i = threadIdx.x; i < nvec; i += 256) {
            float4 v = p[i];
            s  += (v.x + v.y) + (v.z + v.w);
            ss += v.x * v.x + v.y * v.y + v.z * v.z + v.w * v.w;
        }
    }

    // warp reduce
    #pragma unroll
    for (int off = 16; off > 0; off >>= 1) {
        s  += __shfl_xor_sync(0xFFFFFFFFu, s,  off);
        ss += __shfl_xor_sync(0xFFFFFFFFu, ss, off);
    }
    __shared__ float sh_s[8], sh_ss[8];
    const int wid = threadIdx.x >> 5;
    const int lid = threadIdx.x & 31;
    if (lid == 0) { sh_s[wid] = s; sh_ss[wid] = ss; }
    __syncthreads();
    if (wid == 0) {
        s  = (lid < 8) ? sh_s[lid]  : 0.0f;
        ss = (lid < 8) ? sh_ss[lid] : 0.0f;
        #pragma unroll
        for (int off = 4; off > 0; off >>= 1) {
            s  += __shfl_xor_sync(0xFFFFFFFFu, s,  off);
            ss += __shfl_xor_sync(0xFFFFFFFFu, ss, off);
        }
        if (lid == 0 && (s != 0.0f || ss != 0.0f)) {
            atomicAdd(&g_stats[2 * b + 0], s);
            atomicAdd(&g_stats[2 * b + 1], ss);
        }
    }
}

// Pass 2: normalize + affine + mask. grid = (N/4, B), block = 256 threads.
// Each block handles 4 rows; thread t -> row (t/64), float4 column (t%64).
// Invalid rows: write zeros without reading x.
__global__ __launch_bounds__(256) void norm_kernel(const float* __restrict__ x,
                                                   const int* __restrict__ lengths,
                                                   const float* __restrict__ weights,
                                                   const float* __restrict__ biases,
                                                   float* __restrict__ out) {
    const int b = blockIdx.y;
    const int len = lengths[b];
    const int row = blockIdx.x * 4 + (threadIdx.x >> 6);
    const int c = threadIdx.x & 63;  // float4 index within row

    const size_t idx = ((size_t)b * NN + row) * (DD / 4) + c;
    float4* __restrict__ op = reinterpret_cast<float4*>(out);

    if (row >= len) {
        op[idx] = make_float4(0.0f, 0.0f, 0.0f, 0.0f);
        return;
    }

    const float sum   = g_stats[2 * b + 0];
    const float sumsq = g_stats[2 * b + 1];
    const float denom = (float)len * (float)DD;
    const float mean  = sum / denom;
    const float var   = fmaxf(sumsq / denom - mean * mean, 0.0f);
    const float inv   = 1.0f / (sqrtf(var) + EPS);

    const float4 v = reinterpret_cast<const float4*>(x)[idx];
    const float4 w = reinterpret_cast<const float4*>(weights)[c];
    const float4 bi = reinterpret_cast<const float4*>(biases)[c];

    float4 o;
    o.x = (v.x - mean) * inv * w.x + bi.x;
    o.y = (v.y - mean) * inv * w.y + bi.y;
    o.z = (v.z - mean) * inv * w.z + bi.z;
    o.w = (v.w - mean) * inv * w.w + bi.w;
    op[idx] = o;
}

extern "C" void kernel_launch(void* const* d_in, const int* in_sizes, int n_in,
                              void* d_out, int out_size) {
    const float* x        = (const float*)d_in[0];
    const int*   lengths  = (const int*)d_in[1];
    const float* weights  = (const float*)d_in[2];
    const float* biases   = (const float*)d_in[3];
    float* out = (float*)d_out;

    zero_stats_kernel<<<1, 128>>>();
    stats_kernel<<<dim3(CHUNKS, BB), 256>>>(x, lengths);
    norm_kernel<<<dim3(NN / 4, BB), 256>>>(x, lengths, weights, biases, out);
}